// round 2
// baseline (speedup 1.0000x reference)
#include <cuda_runtime.h>
#include <math.h>

// Problem shape (fixed by the dataset): x [2,32,96,96] f32, aff [2,2,4,4] f32,
// out [2,32,96,96,96] f32.
constexpr int kB    = 2;    // batch
constexpr int kC    = 32;   // channels
constexpr int kSP   = 96;   // spatial
constexpr int kNSL  = 2;    // n_slices
constexpr int kCS   = kC / kNSL;        // 16 channels per slice group
constexpr int kSP2  = kSP * kSP;        // 9216
constexpr int kSP3  = kSP * kSP2;       // 884736
constexpr int kWG   = kSP / 4;          // 24 float4 groups per row

// theta[slice*kB + b][12]  (3x4 row-major)
__device__ float g_theta[kNSL * kB][12];

// ---------------------------------------------------------------------------
// Prep: theta = inv( aff * diag(1/zoom_x, 1/zoom_y, 1/zoom_z, 1) )[:3,:]
// Affine with exact [0,0,0,1] bottom row -> inverse = [Rinv | -Rinv t].
// ---------------------------------------------------------------------------
__global__ void prep_theta(const float* __restrict__ aff) {
    int t = threadIdx.x;          // t = slice*kB + b
    if (t >= kNSL * kB) return;
    const float* A = aff + t * 16;

    float zoom[3];
#pragma unroll
    for (int j = 0; j < 3; j++) {
        float a0 = A[0 * 4 + j], a1 = A[1 * 4 + j], a2 = A[2 * 4 + j];
        zoom[j] = sqrtf(a0 * a0 + a1 * a1 + a2 * a2);
    }
    float M[3][4];
#pragma unroll
    for (int i = 0; i < 3; i++) {
#pragma unroll
        for (int j = 0; j < 4; j++) {
            float v = A[i * 4 + j];
            if (j < 3) v /= zoom[j];
            M[i][j] = v;
        }
    }
    float a = M[0][0], b = M[0][1], c = M[0][2];
    float d = M[1][0], e = M[1][1], f = M[1][2];
    float g = M[2][0], h = M[2][1], i = M[2][2];
    float det = a * (e * i - f * h) - b * (d * i - f * g) + c * (d * h - e * g);
    float id  = 1.0f / det;
    float R00 = (e * i - f * h) * id, R01 = (c * h - b * i) * id, R02 = (b * f - c * e) * id;
    float R10 = (f * g - d * i) * id, R11 = (a * i - c * g) * id, R12 = (c * d - a * f) * id;
    float R20 = (d * h - e * g) * id, R21 = (b * g - a * h) * id, R22 = (a * e - b * d) * id;
    float tx = M[0][3], ty = M[1][3], tz = M[2][3];

    float* T = g_theta[t];
    T[0] = R00; T[1] = R01; T[2]  = R02; T[3]  = -(R00 * tx + R01 * ty + R02 * tz);
    T[4] = R10; T[5] = R11; T[6]  = R12; T[7]  = -(R10 * tx + R11 * ty + R12 * tz);
    T[8] = R20; T[9] = R21; T[10] = R22; T[11] = -(R20 * tx + R21 * ty + R22 * tz);
}

// ---------------------------------------------------------------------------
// Main: one thread per (b, slice, d, h, 4-wide w group). Geometry computed
// once per thread, reused across 16 channels; 16 float4 stores per thread.
// ---------------------------------------------------------------------------
__global__ void __launch_bounds__(256) skip_connector_kernel(
    const float* __restrict__ x, float* __restrict__ out) {

    int tid = blockIdx.x * blockDim.x + threadIdx.x;
    // total = kNSL*kB * kSP*kSP*kWG = 884736, launched exactly

    int wg   = tid % kWG;
    int rest = tid / kWG;
    int h    = rest % kSP;
    rest    /= kSP;
    int d    = rest % kSP;
    int bs   = rest / kSP;            // 0..3 = b*kNSL + sl
    int b    = bs / kNSL;
    int sl   = bs % kNSL;

    const float* T = g_theta[sl * kB + b];
    const float s  = 2.0f / kSP;

    float zn  = (d + 0.5f) * s - 1.0f;
    float yn  = (h + 0.5f) * s - 1.0f;
    int   w0  = wg * 4;
    float xn0 = (w0 + 0.5f) * s - 1.0f;

    float gx0 = T[0] * xn0 + T[1] * yn + T[2]  * zn + T[3];
    float gy0 = T[4] * xn0 + T[5] * yn + T[6]  * zn + T[7];
    float gz0 = T[8] * xn0 + T[9] * yn + T[10] * zn + T[11];
    float gxs = T[0] * s, gys = T[4] * s, gzs = T[8] * s;

    float w48[4];
    float wt[4][4];
    int   off[4][4];
    bool  any = false;

#pragma unroll
    for (int j = 0; j < 4; j++) {
        float gx = gx0 + j * gxs;
        float ix = ((gx + 1.0f) * (float)kSP - 1.0f) * 0.5f;
        float fl = floorf(ix);
        float fx = ix - fl;
        // weight of the tap hitting the data plane at W-index 48
        float wxv = (fl == 48.0f) ? (1.0f - fx) : ((fl == 47.0f) ? fx : 0.0f);
        w48[j] = wxv;
#pragma unroll
        for (int k = 0; k < 4; k++) { wt[j][k] = 0.0f; off[j][k] = 0; }
        if (wxv > 0.0f) {
            any = true;
            float gy = gy0 + j * gys;
            float gz = gz0 + j * gzs;
            float iy = ((gy + 1.0f) * (float)kSP - 1.0f) * 0.5f;
            float iz = ((gz + 1.0f) * (float)kSP - 1.0f) * 0.5f;
            float fly = floorf(iy), flz = floorf(iz);
            float fy = iy - fly, fz = iz - flz;
            int iy0 = (int)fly, iz0 = (int)flz;
#pragma unroll
            for (int k = 0; k < 4; k++) {
                int dy = k & 1, dz = k >> 1;
                int yy = iy0 + dy, zz = iz0 + dz;
                bool v   = (yy >= 0) && (yy < kSP) && (zz >= 0) && (zz < kSP);
                float wv = (dz ? fz : 1.0f - fz) * (dy ? fy : 1.0f - fy) * wxv;
                wt[j][k]  = v ? wv : 0.0f;
                int yc = min(max(yy, 0), kSP - 1);
                int zc = min(max(zz, 0), kSP - 1);
                off[j][k] = zc * kSP + yc;
            }
        }
    }

    size_t out_base = (size_t)(b * kC + sl * kCS) * kSP3
                    + (size_t)d * kSP2 + (size_t)h * kSP + w0;

    if (!any) {
        float4 z = make_float4(0.f, 0.f, 0.f, 0.f);
#pragma unroll
        for (int c = 0; c < kCS; c++)
            *reinterpret_cast<float4*>(out + out_base + (size_t)c * kSP3) = z;
        return;
    }

    const float* xb = x + (size_t)(b * kC + sl * kCS) * kSP2;
#pragma unroll
    for (int c = 0; c < kCS; c++) {
        const float* xc = xb + (size_t)c * kSP2;
        float v[4];
#pragma unroll
        for (int j = 0; j < 4; j++) {
            float acc = 0.0f;
            if (w48[j] > 0.0f) {
                acc = wt[j][0] * __ldg(xc + off[j][0])
                    + wt[j][1] * __ldg(xc + off[j][1])
                    + wt[j][2] * __ldg(xc + off[j][2])
                    + wt[j][3] * __ldg(xc + off[j][3]);
            }
            v[j] = acc;
        }
        float4 o = make_float4(v[0], v[1], v[2], v[3]);
        *reinterpret_cast<float4*>(out + out_base + (size_t)c * kSP3) = o;
    }
}

extern "C" void kernel_launch(void* const* d_in, const int* in_sizes, int n_in,
                              void* d_out, int out_size) {
    const float* x   = (const float*)d_in[0];
    const float* aff = (const float*)d_in[1];
    float* out       = (float*)d_out;

    prep_theta<<<1, 4>>>(aff);

    const int total  = kNSL * kB * kSP * kSP * kWG;   // 884736
    const int threads = 256;
    const int blocks  = total / threads;              // 3456 exactly
    skip_connector_kernel<<<blocks, threads>>>(x, out);
}

// round 3
// speedup vs baseline: 1.1361x; 1.1361x over previous
#include <cuda_runtime.h>
#include <math.h>

// Shapes fixed by dataset: x [2,32,96,96] f32, aff [2,2,4,4] f32,
// out [2,32,96,96,96] f32.
constexpr int kB   = 2;
constexpr int kC   = 32;
constexpr int kSP  = 96;
constexpr int kNSL = 2;
constexpr int kCS  = kC / kNSL;   // 16
constexpr int kSP2 = kSP * kSP;   // 9216
constexpr int kSP3 = kSP * kSP2;  // 884736

__device__ float g_theta[kNSL * kB][12];

// ---------------------------------------------------------------------------
// Prep: theta = inv( aff * diag(1/zoom,1) )[:3,:]
// ---------------------------------------------------------------------------
__global__ void prep_theta(const float* __restrict__ aff) {
    int t = threadIdx.x;
    if (t >= kNSL * kB) return;
    const float* A = aff + t * 16;

    float zoom[3];
#pragma unroll
    for (int j = 0; j < 3; j++) {
        float a0 = A[j], a1 = A[4 + j], a2 = A[8 + j];
        zoom[j] = sqrtf(a0 * a0 + a1 * a1 + a2 * a2);
    }
    float M[3][4];
#pragma unroll
    for (int i = 0; i < 3; i++)
#pragma unroll
        for (int j = 0; j < 4; j++) {
            float v = A[i * 4 + j];
            if (j < 3) v /= zoom[j];
            M[i][j] = v;
        }
    float a = M[0][0], b = M[0][1], c = M[0][2];
    float d = M[1][0], e = M[1][1], f = M[1][2];
    float g = M[2][0], h = M[2][1], i = M[2][2];
    float det = a * (e * i - f * h) - b * (d * i - f * g) + c * (d * h - e * g);
    float id  = 1.0f / det;
    float R00 = (e * i - f * h) * id, R01 = (c * h - b * i) * id, R02 = (b * f - c * e) * id;
    float R10 = (f * g - d * i) * id, R11 = (a * i - c * g) * id, R12 = (c * d - a * f) * id;
    float R20 = (d * h - e * g) * id, R21 = (b * g - a * h) * id, R22 = (a * e - b * d) * id;
    float tx = M[0][3], ty = M[1][3], tz = M[2][3];

    float* T = g_theta[t];
    T[0] = R00; T[1] = R01; T[2]  = R02; T[3]  = -(R00 * tx + R01 * ty + R02 * tz);
    T[4] = R10; T[5] = R11; T[6]  = R12; T[7]  = -(R10 * tx + R11 * ty + R12 * tz);
    T[8] = R20; T[9] = R21; T[10] = R22; T[11] = -(R20 * tx + R21 * ty + R22 * tz);
}

// ---------------------------------------------------------------------------
// Pass 1: pure zero-fill at max store bandwidth. 8 float4 per thread.
// total float4 = 2*32*96^3/4 = 14155776 = 6912 blocks * 256 thr * 8.
// ---------------------------------------------------------------------------
__global__ void __launch_bounds__(256) zero_fill(float4* __restrict__ out) {
    size_t base = (size_t)blockIdx.x * (256 * 8) + threadIdx.x;
    float4 z = make_float4(0.f, 0.f, 0.f, 0.f);
#pragma unroll
    for (int k = 0; k < 8; k++)
        out[base + (size_t)k * 256] = z;
}

// ---------------------------------------------------------------------------
// Pass 2: sparse scatter. One thread per (bs, d, h, w) voxel. ~98% of
// threads exit after ~15 flops (x-tap weight == 0). Hitting threads do a
// 4-tap bilinear gather on x for each of 16 channels and store 16 scalars.
// ---------------------------------------------------------------------------
__global__ void __launch_bounds__(256) sparse_scatter(
    const float* __restrict__ x, float* __restrict__ out) {

    int tid = blockIdx.x * blockDim.x + threadIdx.x;  // total 4*96^3
    int w    = tid % kSP;
    int rest = tid / kSP;
    int h    = rest % kSP;
    rest    /= kSP;
    int d    = rest % kSP;
    int bs   = rest / kSP;     // b*kNSL + sl
    int b    = bs >> 1;
    int sl   = bs & 1;

    const float* T = g_theta[sl * kB + b];
    const float s  = 2.0f / kSP;

    float xn = (w + 0.5f) * s - 1.0f;
    float yn = (h + 0.5f) * s - 1.0f;
    float zn = (d + 0.5f) * s - 1.0f;

    float gx = T[0] * xn + T[1] * yn + T[2]  * zn + T[3];
    float ix = ((gx + 1.0f) * (float)kSP - 1.0f) * 0.5f;
    float fl = floorf(ix);
    float fx = ix - fl;
    // weight of the trilinear tap hitting the data plane at W-index 48
    float wx = (fl == 48.0f) ? (1.0f - fx) : ((fl == 47.0f) ? fx : 0.0f);
    if (wx <= 0.0f) return;

    float gy = T[4] * xn + T[5] * yn + T[6]  * zn + T[7];
    float gz = T[8] * xn + T[9] * yn + T[10] * zn + T[11];
    float iy = ((gy + 1.0f) * (float)kSP - 1.0f) * 0.5f;
    float iz = ((gz + 1.0f) * (float)kSP - 1.0f) * 0.5f;
    float fly = floorf(iy), flz = floorf(iz);
    float fy = iy - fly,    fz = iz - flz;
    int iy0 = (int)fly, iz0 = (int)flz;

    float wt[4];
    int   off[4];
#pragma unroll
    for (int k = 0; k < 4; k++) {
        int dy = k & 1, dz = k >> 1;
        int yy = iy0 + dy, zz = iz0 + dz;
        bool v = (yy >= 0) && (yy < kSP) && (zz >= 0) && (zz < kSP);
        float wv = (dz ? fz : 1.0f - fz) * (dy ? fy : 1.0f - fy) * wx;
        wt[k]  = v ? wv : 0.0f;
        int yc = min(max(yy, 0), kSP - 1);
        int zc = min(max(zz, 0), kSP - 1);
        off[k] = zc * kSP + yc;
    }

    const float* xb = x + (size_t)(b * kC + sl * kCS) * kSP2;
    size_t out_base = (size_t)(b * kC + sl * kCS) * kSP3
                    + (size_t)d * kSP2 + (size_t)h * kSP + w;

#pragma unroll
    for (int c = 0; c < kCS; c++) {
        const float* xc = xb + c * kSP2;
        float acc = wt[0] * __ldg(xc + off[0])
                  + wt[1] * __ldg(xc + off[1])
                  + wt[2] * __ldg(xc + off[2])
                  + wt[3] * __ldg(xc + off[3]);
        out[out_base + (size_t)c * kSP3] = acc;
    }
}

extern "C" void kernel_launch(void* const* d_in, const int* in_sizes, int n_in,
                              void* d_out, int out_size) {
    const float* x   = (const float*)d_in[0];
    const float* aff = (const float*)d_in[1];
    float* out       = (float*)d_out;

    prep_theta<<<1, 4>>>(aff);

    // Pass 1: zero-fill 2*32*96^3 floats = 14155776 float4
    zero_fill<<<6912, 256>>>((float4*)out);

    // Pass 2: sparse scatter over 4*96^3 voxels
    const int total = kNSL * kB * kSP3;     // 3538944
    sparse_scatter<<<total / 256, 256>>>(x, out);
}

// round 4
// speedup vs baseline: 1.2504x; 1.1005x over previous
#include <cuda_runtime.h>
#include <math.h>

// Shapes fixed by dataset: x [2,32,96,96] f32, aff [2,2,4,4] f32,
// out [2,32,96,96,96] f32.
constexpr int kB   = 2;
constexpr int kC   = 32;
constexpr int kSP  = 96;
constexpr int kNSL = 2;
constexpr int kCS  = kC / kNSL;   // 16
constexpr int kSP2 = kSP * kSP;   // 9216
constexpr int kSP3 = kSP * kSP2;  // 884736

// ---------------------------------------------------------------------------
// theta = inv( aff * diag(1/zoom,1) )[:3,:]   (device helper, ~60 flops)
// ---------------------------------------------------------------------------
__device__ __forceinline__ void compute_theta(const float* __restrict__ A,
                                              float* __restrict__ T) {
    float zoom[3];
#pragma unroll
    for (int j = 0; j < 3; j++) {
        float a0 = A[j], a1 = A[4 + j], a2 = A[8 + j];
        zoom[j] = sqrtf(a0 * a0 + a1 * a1 + a2 * a2);
    }
    float M[3][4];
#pragma unroll
    for (int i = 0; i < 3; i++)
#pragma unroll
        for (int j = 0; j < 4; j++) {
            float v = A[i * 4 + j];
            if (j < 3) v /= zoom[j];
            M[i][j] = v;
        }
    float a = M[0][0], b = M[0][1], c = M[0][2];
    float d = M[1][0], e = M[1][1], f = M[1][2];
    float g = M[2][0], h = M[2][1], i = M[2][2];
    float det = a * (e * i - f * h) - b * (d * i - f * g) + c * (d * h - e * g);
    float id  = 1.0f / det;
    float R00 = (e * i - f * h) * id, R01 = (c * h - b * i) * id, R02 = (b * f - c * e) * id;
    float R10 = (f * g - d * i) * id, R11 = (a * i - c * g) * id, R12 = (c * d - a * f) * id;
    float R20 = (d * h - e * g) * id, R21 = (b * g - a * h) * id, R22 = (a * e - b * d) * id;
    float tx = M[0][3], ty = M[1][3], tz = M[2][3];
    T[0] = R00; T[1] = R01; T[2]  = R02; T[3]  = -(R00 * tx + R01 * ty + R02 * tz);
    T[4] = R10; T[5] = R11; T[6]  = R12; T[7]  = -(R10 * tx + R11 * ty + R12 * tz);
    T[8] = R20; T[9] = R21; T[10] = R22; T[11] = -(R20 * tx + R21 * ty + R22 * tz);
}

// ---------------------------------------------------------------------------
// Pass 1: pure zero-fill at max store bandwidth. Warp-contiguous float4
// stores (512B per STG.128). 8 float4 per thread.
// ---------------------------------------------------------------------------
__global__ void __launch_bounds__(256) zero_fill(float4* __restrict__ out) {
    size_t base = (size_t)blockIdx.x * (256 * 8) + threadIdx.x;
    float4 z = make_float4(0.f, 0.f, 0.f, 0.f);
#pragma unroll
    for (int k = 0; k < 8; k++)
        out[base + (size_t)k * 256] = z;
}

// ---------------------------------------------------------------------------
// Pass 2: interval scatter. One thread per (bs, d, c, h). ix(w) is linear in
// w, so the hit set {w : ix in (47,49)} is a contiguous interval computed in
// closed form, widened +-1, and each candidate w rechecked with the exact
// per-voxel formula (bit-identical to the reference path).
// ---------------------------------------------------------------------------
__global__ void __launch_bounds__(256) sparse_scatter(
    const float* __restrict__ x, const float* __restrict__ aff,
    float* __restrict__ out) {

    // gid -> (bs, d, c, h); 96*16*96 = 147456 per bs, divisible by 256,
    // so bs is constant within a block.
    int gid  = blockIdx.x * blockDim.x + threadIdx.x;
    int h    = gid % kSP;
    int rest = gid / kSP;
    int c    = rest % kCS;
    rest    /= kCS;
    int d    = rest % kSP;
    int bs   = rest / kSP;      // b*kNSL + sl
    int b    = bs >> 1;
    int sl   = bs & 1;

    __shared__ float T[12];
    if (threadIdx.x == 0)
        compute_theta(aff + (sl * kB + b) * 16, T);
    __syncthreads();

    const float s = 2.0f / kSP;
    float yn = (h + 0.5f) * s - 1.0f;
    float zn = (d + 0.5f) * s - 1.0f;

    float gxb = T[1] * yn + T[2]  * zn + T[3];
    float gyb = T[5] * yn + T[6]  * zn + T[7];
    float gzb = T[9] * yn + T[10] * zn + T[11];

    // ix(w) = 48*gx(w) + 47.5, gx(w) = T0*((w+0.5)*s - 1) + gxb
    float c1 = 48.0f * T[0] * s;                              // slope dix/dw
    float c0 = 48.0f * (T[0] * (0.5f * s - 1.0f) + gxb) + 47.5f;

    int wlo, whi;
    if (fabsf(c1) < 1e-7f) {
        if (c0 > 47.0f && c0 < 49.0f) { wlo = 0; whi = kSP - 1; }
        else return;
    } else {
        float wa = (47.0f - c0) / c1;
        float wb = (49.0f - c0) / c1;
        float lo = fminf(wa, wb), hi = fmaxf(wa, wb);
        wlo = max(0,        (int)floorf(lo) - 1);
        whi = min(kSP - 1,  (int)floorf(hi) + 1);
        if (wlo > whi) return;
    }

    const float* xc = x + (size_t)(b * kC + sl * kCS + c) * kSP2;
    size_t out_base = (size_t)(b * kC + sl * kCS + c) * kSP3
                    + (size_t)d * kSP2 + (size_t)h * kSP;

    for (int w = wlo; w <= whi; w++) {
        float xn = (w + 0.5f) * s - 1.0f;
        float gx = T[0] * xn + gxb;
        float ix = ((gx + 1.0f) * (float)kSP - 1.0f) * 0.5f;
        float fl = floorf(ix);
        float fx = ix - fl;
        float wx = (fl == 48.0f) ? (1.0f - fx) : ((fl == 47.0f) ? fx : 0.0f);
        if (wx <= 0.0f) continue;

        float gy = T[4] * xn + gyb;
        float gz = T[8] * xn + gzb;
        float iy = ((gy + 1.0f) * (float)kSP - 1.0f) * 0.5f;
        float iz = ((gz + 1.0f) * (float)kSP - 1.0f) * 0.5f;
        float fly = floorf(iy), flz = floorf(iz);
        float fy = iy - fly,    fz = iz - flz;
        int iy0 = (int)fly, iz0 = (int)flz;

        float acc = 0.0f;
#pragma unroll
        for (int k = 0; k < 4; k++) {
            int dy = k & 1, dz = k >> 1;
            int yy = iy0 + dy, zz = iz0 + dz;
            bool v = (yy >= 0) && (yy < kSP) && (zz >= 0) && (zz < kSP);
            float wv = (dz ? fz : 1.0f - fz) * (dy ? fy : 1.0f - fy) * wx;
            int yc = min(max(yy, 0), kSP - 1);
            int zc = min(max(zz, 0), kSP - 1);
            acc += (v ? wv : 0.0f) * __ldg(xc + zc * kSP + yc);
        }
        out[out_base + w] = acc;
    }
}

extern "C" void kernel_launch(void* const* d_in, const int* in_sizes, int n_in,
                              void* d_out, int out_size) {
    const float* x   = (const float*)d_in[0];
    const float* aff = (const float*)d_in[1];
    float* out       = (float*)d_out;

    // Pass 1: zero-fill 2*32*96^3 floats = 14155776 float4
    zero_fill<<<6912, 256>>>((float4*)out);

    // Pass 2: interval scatter, one thread per (bs, d, c, h)
    const int total = kNSL * kB * kSP * kCS * kSP;   // 589824
    sparse_scatter<<<total / 256, 256>>>(x, aff, out);
}

// round 5
// speedup vs baseline: 1.8852x; 1.5077x over previous
#include <cuda_runtime.h>
#include <math.h>

// Shapes fixed by dataset: x [2,32,96,96] f32, aff [2,2,4,4] f32,
// out [2,32,96,96,96] f32.
constexpr int kB   = 2;
constexpr int kC   = 32;
constexpr int kSP  = 96;
constexpr int kNSL = 2;
constexpr int kCS  = kC / kNSL;   // 16
constexpr int kSP2 = kSP * kSP;   // 9216
constexpr int kSP3 = kSP * kSP2;  // 884736

// ---------------------------------------------------------------------------
// theta = inv( aff * diag(1/zoom,1) )[:3,:]
// ---------------------------------------------------------------------------
__device__ __forceinline__ void compute_theta(const float* __restrict__ A,
                                              float* __restrict__ T) {
    float zoom[3];
#pragma unroll
    for (int j = 0; j < 3; j++) {
        float a0 = A[j], a1 = A[4 + j], a2 = A[8 + j];
        zoom[j] = sqrtf(a0 * a0 + a1 * a1 + a2 * a2);
    }
    float M[3][4];
#pragma unroll
    for (int i = 0; i < 3; i++)
#pragma unroll
        for (int j = 0; j < 4; j++) {
            float v = A[i * 4 + j];
            if (j < 3) v /= zoom[j];
            M[i][j] = v;
        }
    float a = M[0][0], b = M[0][1], c = M[0][2];
    float d = M[1][0], e = M[1][1], f = M[1][2];
    float g = M[2][0], h = M[2][1], i = M[2][2];
    float det = a * (e * i - f * h) - b * (d * i - f * g) + c * (d * h - e * g);
    float id  = 1.0f / det;
    float R00 = (e * i - f * h) * id, R01 = (c * h - b * i) * id, R02 = (b * f - c * e) * id;
    float R10 = (f * g - d * i) * id, R11 = (a * i - c * g) * id, R12 = (c * d - a * f) * id;
    float R20 = (d * h - e * g) * id, R21 = (b * g - a * h) * id, R22 = (a * e - b * d) * id;
    float tx = M[0][3], ty = M[1][3], tz = M[2][3];
    T[0] = R00; T[1] = R01; T[2]  = R02; T[3]  = -(R00 * tx + R01 * ty + R02 * tz);
    T[4] = R10; T[5] = R11; T[6]  = R12; T[7]  = -(R10 * tx + R11 * ty + R12 * tz);
    T[8] = R20; T[9] = R21; T[10] = R22; T[11] = -(R20 * tx + R21 * ty + R22 * tz);
}

// ---------------------------------------------------------------------------
// Fused kernel. One warp owns 32 consecutive h-rows of one (b,ch,d) slice
// (a contiguous 12KB output block).
//   Phase 1: coalesced zero-fill of the 12KB region (24 STG.128 per lane).
//   Phase 2: per-lane slab interval -> overwrite the ~3 nonzero scalars.
// Warps per (bs,d): 16 c * 3 h-groups = 48; blocks of 8 warps stay within
// one (bs,d), so one theta per block.
// ---------------------------------------------------------------------------
__global__ void __launch_bounds__(256) skip_fused(
    const float* __restrict__ x, const float* __restrict__ aff,
    float* __restrict__ out) {

    int warp = blockIdx.x * 8 + (threadIdx.x >> 5);
    int lane = threadIdx.x & 31;

    int hg   = warp % 3;          // h-group: h0 = hg*32
    int rest = warp / 3;
    int c    = rest % kCS;
    rest    /= kCS;
    int d    = rest % kSP;
    int bs   = rest / kSP;        // b*kNSL + sl
    int b    = bs >> 1;
    int sl   = bs & 1;

    __shared__ float T[12];
    if (threadIdx.x == 0)
        compute_theta(aff + (sl * kB + b) * 16, T);
    __syncthreads();

    int ch_global = b * kC + sl * kCS + c;
    int h0 = hg * 32;
    size_t base = (size_t)ch_global * kSP3 + (size_t)d * kSP2 + (size_t)h0 * kSP;

    // ---- Phase 1: coalesced zero-fill of 32 rows (12288 B) ----
    float4* o4 = reinterpret_cast<float4*>(out + base);
    float4 z = make_float4(0.f, 0.f, 0.f, 0.f);
#pragma unroll
    for (int i = 0; i < 24; i++)
        o4[i * 32 + lane] = z;

    __threadfence_block();
    __syncwarp();

    // ---- Phase 2: per-lane slab interval on row h = h0 + lane ----
    int h = h0 + lane;
    const float s = 2.0f / kSP;
    float yn = (h + 0.5f) * s - 1.0f;
    float zn = (d + 0.5f) * s - 1.0f;

    float gxb = T[1] * yn + T[2]  * zn + T[3];
    float gyb = T[5] * yn + T[6]  * zn + T[7];
    float gzb = T[9] * yn + T[10] * zn + T[11];

    // ix(w) = 48*gx(w) + 47.5
    float c1 = 48.0f * T[0] * s;
    float c0 = 48.0f * (T[0] * (0.5f * s - 1.0f) + gxb) + 47.5f;

    int wlo, whi;
    bool none = false;
    if (fabsf(c1) < 1e-7f) {
        if (c0 > 47.0f && c0 < 49.0f) { wlo = 0; whi = kSP - 1; }
        else none = true;
    } else {
        float wa = (47.0f - c0) / c1;
        float wb = (49.0f - c0) / c1;
        float lo = fminf(wa, wb), hi = fmaxf(wa, wb);
        wlo = max(0,       (int)floorf(lo) - 1);
        whi = min(kSP - 1, (int)floorf(hi) + 1);
        if (wlo > whi) none = true;
    }

    if (!none) {
        const float* xc = x + (size_t)ch_global * kSP2;
        float* orow = out + base + (size_t)lane * kSP;

        for (int w = wlo; w <= whi; w++) {
            float xn = (w + 0.5f) * s - 1.0f;
            float gx = T[0] * xn + gxb;
            float ix = ((gx + 1.0f) * (float)kSP - 1.0f) * 0.5f;
            float fl = floorf(ix);
            float fx = ix - fl;
            float wx = (fl == 48.0f) ? (1.0f - fx) : ((fl == 47.0f) ? fx : 0.0f);
            if (wx <= 0.0f) continue;

            float gy = T[4] * xn + gyb;
            float gz = T[8] * xn + gzb;
            float iy = ((gy + 1.0f) * (float)kSP - 1.0f) * 0.5f;
            float iz = ((gz + 1.0f) * (float)kSP - 1.0f) * 0.5f;
            float fly = floorf(iy), flz = floorf(iz);
            float fy = iy - fly,    fz = iz - flz;
            int iy0 = (int)fly, iz0 = (int)flz;

            float acc = 0.0f;
#pragma unroll
            for (int k = 0; k < 4; k++) {
                int dy = k & 1, dz = k >> 1;
                int yy = iy0 + dy, zz = iz0 + dz;
                bool v = (yy >= 0) && (yy < kSP) && (zz >= 0) && (zz < kSP);
                float wv = (dz ? fz : 1.0f - fz) * (dy ? fy : 1.0f - fy) * wx;
                int yc = min(max(yy, 0), kSP - 1);
                int zc = min(max(zz, 0), kSP - 1);
                acc += (v ? wv : 0.0f) * __ldg(xc + zc * kSP + yc);
            }
            orow[w] = acc;
        }
    }
}

extern "C" void kernel_launch(void* const* d_in, const int* in_sizes, int n_in,
                              void* d_out, int out_size) {
    const float* x   = (const float*)d_in[0];
    const float* aff = (const float*)d_in[1];
    float* out       = (float*)d_out;

    // warps = kNSL*kB * kSP(d) * kCS(c) * 3(h-groups) = 18432 -> 2304 blocks
    const int warps  = kNSL * kB * kSP * kCS * 3;
    skip_fused<<<warps / 8, 256>>>(x, aff, out);
}